// round 1
// baseline (speedup 1.0000x reference)
#include <cuda_runtime.h>
#include <cuda_bf16.h>
#include <cstdint>
#include <cstddef>

#define OBS_LEN 16
#define PRED_LEN 25
#define NNODES 192
#define PP (NNODES * NNODES)
#define ENC 64
#define DEC 128
#define EMB 32
#define DYN 32
#define SOC 144

// ---------------- scratch (device globals: no allocation allowed) ----------------
__device__ float g_Hngbr[PP * ENC];        // 9.4 MB
__device__ float g_Hego[NNODES * ENC];
__device__ float g_dyn[NNODES * DYN];
__device__ float g_soc[NNODES * SOC];
__device__ float g_z0[NNODES * 4 * DEC];
__device__ float g_WTd[DEC * 4 * DEC];     // Whh_d transposed [k][j]

__device__ __forceinline__ float sigf(float x) { return 1.f / (1.f + expf(-x)); }
__device__ __forceinline__ float lrelu(float x) { return x >= 0.f ? x : 0.1f * x; }

// ---------------- encoder LSTM: 64 rows/block = 16 warps x 4 rows ----------------
// x: [16][tot][2]. Weights transposed into shared for conflict-free loads.
// Lane l owns z[l] and z[l+32] of each of the 4 gates -> shuffle-free c/h update.
__global__ void __launch_bounds__(512) enc_lstm_kernel(
    const float* __restrict__ x,
    const float* __restrict__ Wip, const float* __restrict__ bip,
    const float* __restrict__ Wih, const float* __restrict__ Whh,
    const float* __restrict__ bih, const float* __restrict__ bhh,
    float* __restrict__ Hout, int tot)
{
    extern __shared__ float sm[];
    float* WT_ih = sm;              // 32*256 = 8192
    float* WT_hh = sm + 8192;       // 64*256 = 16384
    float* bsum  = sm + 24576;      // 256
    float* Wip_s = sm + 24832;      // 64
    float* bip_s = sm + 24896;      // 32
    float* emb_s = sm + 24928;      // 64 rows * 32
    float* h_s   = sm + 26976;      // 64 rows * 64
    // total 31072 floats = 124288 B

    int tid = threadIdx.x;
    for (int i = tid; i < 256 * 32; i += 512) { int j = i >> 5, k = i & 31; WT_ih[k * 256 + j] = Wih[i]; }
    for (int i = tid; i < 256 * 64; i += 512) { int j = i >> 6, k = i & 63; WT_hh[k * 256 + j] = Whh[i]; }
    for (int i = tid; i < 256; i += 512) bsum[i] = bih[i] + bhh[i];
    if (tid < 64) Wip_s[tid] = Wip[tid];
    if (tid < 32) bip_s[tid] = bip[tid];

    int warp = tid >> 5, lane = tid & 31;
    int wrow = warp * 4;                      // first local row of this warp
    int r0 = blockIdx.x * 64 + wrow;          // first global row

#pragma unroll
    for (int rr = 0; rr < 4; ++rr) {
        h_s[(wrow + rr) * 64 + lane] = 0.f;
        h_s[(wrow + rr) * 64 + lane + 32] = 0.f;
    }
    float c0[4] = {0, 0, 0, 0}, c1[4] = {0, 0, 0, 0};
    __syncthreads();

    for (int t = 0; t < OBS_LEN; ++t) {
        const float* xt = x + (size_t)t * tot * 2;
        // input embedding: lane computes emb[lane] for each of its 4 rows
#pragma unroll
        for (int rr = 0; rr < 4; ++rr) {
            int row = r0 + rr;
            float x0 = xt[row * 2], x1 = xt[row * 2 + 1];
            float v = fmaf(Wip_s[lane * 2], x0, fmaf(Wip_s[lane * 2 + 1], x1, bip_s[lane]));
            emb_s[(wrow + rr) * 32 + lane] = lrelu(v);
        }
        __syncwarp();

        float acc[4][8];
#pragma unroll
        for (int rr = 0; rr < 4; ++rr)
#pragma unroll
            for (int g = 0; g < 8; ++g) acc[rr][g] = bsum[lane + 32 * g];

#pragma unroll 4
        for (int k = 0; k < 32; ++k) {
            float w[8];
#pragma unroll
            for (int g = 0; g < 8; ++g) w[g] = WT_ih[k * 256 + lane + 32 * g];
#pragma unroll
            for (int rr = 0; rr < 4; ++rr) {
                float e = emb_s[(wrow + rr) * 32 + k];
#pragma unroll
                for (int g = 0; g < 8; ++g) acc[rr][g] = fmaf(w[g], e, acc[rr][g]);
            }
        }
#pragma unroll 4
        for (int k = 0; k < 64; ++k) {
            float w[8];
#pragma unroll
            for (int g = 0; g < 8; ++g) w[g] = WT_hh[k * 256 + lane + 32 * g];
#pragma unroll
            for (int rr = 0; rr < 4; ++rr) {
                float hv = h_s[(wrow + rr) * 64 + k];
#pragma unroll
                for (int g = 0; g < 8; ++g) acc[rr][g] = fmaf(w[g], hv, acc[rr][g]);
            }
        }
        __syncwarp();   // all lanes done reading h_s before overwrite

        // gate order i,f,g,o: acc[g]: 0,1 -> i ; 2,3 -> f ; 4,5 -> g ; 6,7 -> o
#pragma unroll
        for (int rr = 0; rr < 4; ++rr) {
            c0[rr] = sigf(acc[rr][2]) * c0[rr] + sigf(acc[rr][0]) * tanhf(acc[rr][4]);
            c1[rr] = sigf(acc[rr][3]) * c1[rr] + sigf(acc[rr][1]) * tanhf(acc[rr][5]);
            float h0 = sigf(acc[rr][6]) * tanhf(c0[rr]);
            float h1 = sigf(acc[rr][7]) * tanhf(c1[rr]);
            h_s[(wrow + rr) * 64 + lane] = h0;
            h_s[(wrow + rr) * 64 + lane + 32] = h1;
        }
        __syncwarp();
    }

#pragma unroll
    for (int rr = 0; rr < 4; ++rr) {
        int row = r0 + rr;
        Hout[row * 64 + lane] = h_s[(wrow + rr) * 64 + lane];
        Hout[row * 64 + lane + 32] = h_s[(wrow + rr) * 64 + lane + 32];
    }
}

// ---------------- traj_enc = lrelu(H_ego @ Wdyn^T + bdyn) ----------------
__global__ void dyn_kernel(const float* __restrict__ H, const float* __restrict__ Wdyn,
                           const float* __restrict__ bdyn, float* __restrict__ out)
{
    int i = blockIdx.x * blockDim.x + threadIdx.x;
    if (i >= NNODES * DYN) return;
    int n = i >> 5, j = i & 31;
    float a = bdyn[j];
    const float* h = H + n * 64;
    const float* w = Wdyn + j * 64;
#pragma unroll 8
    for (int k = 0; k < 64; ++k) a = fmaf(w[k], h[k], a);
    out[i] = lrelu(a);
}

// ---------------- social pipeline: gather + transpose + conv1 + conv2 + maxpool ----------------
// one block per batch element b; 384 threads = 6 output rows x 64 output channels
__global__ void __launch_bounds__(384) social_kernel(
    const float* __restrict__ Hn, const int* __restrict__ midx,
    const float* __restrict__ Wc1, const float* __restrict__ bc1,
    const float* __restrict__ Wc2, const float* __restrict__ bc2,
    float* __restrict__ socout)
{
    extern __shared__ float sm[];
    float* in_s = sm;               // 64ch * 8 * 8 = 4096   layout [c][gw][gh]
    float* w1t  = sm + 4096;        // 36864  layout [c*9+u*3+v][o]
    float* w2t  = sm + 40960;       // 9216   layout [c*9+u*3+v][o]
    float* mid  = sm + 50176;       // 64*36  layout [o][p*6+q]
    float* c2s  = sm + 52480;       // 16*16
    float* bc1s = sm + 52736;       // 64
    float* bc2s = sm + 52800;       // 16
    // total 52816 floats = 211264 B

    int tid = threadIdx.x, b = blockIdx.x;
    for (int i = tid; i < 36864; i += 384) {
        int o = i / 576; int rem = i - o * 576;     // rem = c*9 + u*3 + v
        w1t[rem * 64 + o] = Wc1[i];
    }
    for (int i = tid; i < 9216; i += 384) {
        int o = i / 576; int rem = i - o * 576;
        w2t[rem * 16 + o] = Wc2[i];
    }
    // gather + transpose: soc_t[b][e][gw][gh] = Hn[masks_idxs[b*64 + gh*8 + gw]][e]
    for (int i = tid; i < 4096; i += 384) {
        int e = i & 63; int cell = i >> 6;          // cell = gh*8 + gw
        int gh = cell >> 3, gw = cell & 7;
        int p = midx[b * 64 + cell];
        in_s[e * 64 + gw * 8 + gh] = Hn[p * 64 + e];
    }
    if (tid < 64) bc1s[tid] = bc1[tid];
    if (tid < 16) bc2s[tid] = bc2[tid];
    __syncthreads();

    // conv1: [64,8,8] -> [64,6,6], thread = (p-row g, out channel o)
    {
        int g = tid >> 6, o = tid & 63;
        float acc[6];
#pragma unroll
        for (int q = 0; q < 6; ++q) acc[q] = bc1s[o];
        for (int c = 0; c < 64; ++c) {
#pragma unroll
            for (int u = 0; u < 3; ++u) {
                float iv[8];
#pragma unroll
                for (int j = 0; j < 8; ++j) iv[j] = in_s[c * 64 + (g + u) * 8 + j];
#pragma unroll
                for (int v = 0; v < 3; ++v) {
                    float w = w1t[(c * 9 + u * 3 + v) * 64 + o];
#pragma unroll
                    for (int q = 0; q < 6; ++q) acc[q] = fmaf(w, iv[q + v], acc[q]);
                }
            }
        }
#pragma unroll
        for (int q = 0; q < 6; ++q) mid[o * 36 + g * 6 + q] = lrelu(acc[q]);
    }
    __syncthreads();

    // conv2: [64,6,6] -> [16,4,4]
    if (tid < 256) {
        int o = tid >> 4, pos = tid & 15; int p = pos >> 2, q = pos & 3;
        float acc = bc2s[o];
        for (int c = 0; c < 64; ++c) {
#pragma unroll
            for (int u = 0; u < 3; ++u)
#pragma unroll
                for (int v = 0; v < 3; ++v)
                    acc = fmaf(mid[c * 36 + (p + u) * 6 + (q + v)],
                               w2t[(c * 9 + u * 3 + v) * 16 + o], acc);
        }
        c2s[tid] = lrelu(acc);
    }
    __syncthreads();

    // maxpool 2x2 stride 1: [16,4,4] -> [16,3,3] -> flatten 144
    if (tid < 144) {
        int o = tid / 9, pq = tid - o * 9; int p = pq / 3, q = pq - p * 3;
        const float* base = c2s + o * 16;
        float m = fmaxf(fmaxf(base[p * 4 + q], base[p * 4 + q + 1]),
                        fmaxf(base[(p + 1) * 4 + q], base[(p + 1) * 4 + q + 1]));
        socout[b * 144 + tid] = m;
    }
}

// ---------------- decoder input precompute: z0 = Wih_d @ [traj_enc|soc] + bih + bhh ----------------
__global__ void z0_kernel(const float* __restrict__ dyn, const float* __restrict__ soc,
                          const float* __restrict__ Wih_d, const float* __restrict__ bih_d,
                          const float* __restrict__ bhh_d, float* __restrict__ z0)
{
    int i = blockIdx.x * blockDim.x + threadIdx.x;
    if (i >= NNODES * 512) return;
    int n = i >> 9, j = i & 511;
    float a = bih_d[j] + bhh_d[j];
    const float* w = Wih_d + j * 176;
    const float* d = dyn + n * 32;
    const float* s = soc + n * 144;
#pragma unroll 4
    for (int k = 0; k < 32; ++k) a = fmaf(w[k], d[k], a);
#pragma unroll 4
    for (int k = 0; k < 144; ++k) a = fmaf(w[32 + k], s[k], a);
    z0[i] = a;
}

__global__ void transpose_whhd(const float* __restrict__ Whh_d, float* __restrict__ WT)
{
    int i = blockIdx.x * blockDim.x + threadIdx.x;
    if (i >= 512 * 128) return;
    int j = i >> 7, k = i & 127;
    WT[k * 512 + j] = Whh_d[i];
}

// ---------------- decoder LSTM: 2 rows/block, 512 threads (thread j owns z_j) ----------------
__global__ void __launch_bounds__(512) dec_kernel(
    const float* __restrict__ z0, const float* __restrict__ WT,
    const float* __restrict__ Wop, const float* __restrict__ bop,
    float* __restrict__ out)
{
    __shared__ float h_s[2][128];
    __shared__ float z_s[2][512];
    int tid = threadIdx.x;
    int b0 = blockIdx.x * 2;
    float zin0 = z0[b0 * 512 + tid];
    float zin1 = z0[(b0 + 1) * 512 + tid];
    float c = 0.f;
    if (tid < 256) h_s[tid >> 7][tid & 127] = 0.f;
    __syncthreads();

    for (int t = 0; t < PRED_LEN; ++t) {
        float a0 = zin0, a1 = zin1;
#pragma unroll 8
        for (int k = 0; k < 128; ++k) {
            float w = WT[k * 512 + tid];           // coalesced, L2-resident
            a0 = fmaf(w, h_s[0][k], a0);
            a1 = fmaf(w, h_s[1][k], a1);
        }
        z_s[0][tid] = a0; z_s[1][tid] = a1;
        __syncthreads();
        if (tid < 256) {
            int r = tid >> 7, m = tid & 127;
            float zi = z_s[r][m], zf = z_s[r][128 + m];
            float zg = z_s[r][256 + m], zo = z_s[r][384 + m];
            c = sigf(zf) * c + sigf(zi) * tanhf(zg);
            h_s[r][m] = sigf(zo) * tanhf(c);
        }
        __syncthreads();
        // output projection: 10 warps, warp = (row r, out index oi)
        if (tid < 320) {
            int wp = tid >> 5, lane = tid & 31;
            int r = wp / 5, oi = wp - r * 5;
            float a = 0.f;
#pragma unroll
            for (int k = lane; k < 128; k += 32) a = fmaf(Wop[oi * 128 + k], h_s[r][k], a);
#pragma unroll
            for (int s = 16; s; s >>= 1) a += __shfl_down_sync(0xffffffffu, a, s);
            if (lane == 0) {
                a += bop[oi];
                float v = (oi == 2 || oi == 3) ? expf(a) : (oi == 4 ? tanhf(a) : a);
                out[((size_t)t * NNODES + b0 + r) * 5 + oi] = v;
            }
        }
    }
}

// ---------------- launcher ----------------
extern "C" void kernel_launch(void* const* d_in, const int* in_sizes, int n_in,
                              void* d_out, int out_size)
{
    // input 6 is num_nodes (size-1) if the converter kept the python int; weights follow
    int wi = (n_in > 6 && in_sizes[6] == 1) ? 7 : 6;

    const float* obs_traj  = (const float*)d_in[0];
    const float* obs_ngbrs = (const float*)d_in[1];
    const int*   midx      = (const int*)d_in[3];
    const float* Wip   = (const float*)d_in[wi + 0];
    const float* bip   = (const float*)d_in[wi + 1];
    const float* Wih_e = (const float*)d_in[wi + 2];
    const float* Whh_e = (const float*)d_in[wi + 3];
    const float* bih_e = (const float*)d_in[wi + 4];
    const float* bhh_e = (const float*)d_in[wi + 5];
    const float* Wdyn  = (const float*)d_in[wi + 6];
    const float* bdyn  = (const float*)d_in[wi + 7];
    const float* Wc1   = (const float*)d_in[wi + 8];
    const float* bc1   = (const float*)d_in[wi + 9];
    const float* Wc2   = (const float*)d_in[wi + 10];
    const float* bc2   = (const float*)d_in[wi + 11];
    const float* Wih_d = (const float*)d_in[wi + 12];
    const float* Whh_d = (const float*)d_in[wi + 13];
    const float* bih_d = (const float*)d_in[wi + 14];
    const float* bhh_d = (const float*)d_in[wi + 15];
    const float* Wop   = (const float*)d_in[wi + 16];
    const float* bop   = (const float*)d_in[wi + 17];
    float* out = (float*)d_out;

    float *Hn, *He, *dynb, *socb, *z0b, *WTb;
    cudaGetSymbolAddress((void**)&Hn,   g_Hngbr);
    cudaGetSymbolAddress((void**)&He,   g_Hego);
    cudaGetSymbolAddress((void**)&dynb, g_dyn);
    cudaGetSymbolAddress((void**)&socb, g_soc);
    cudaGetSymbolAddress((void**)&z0b,  g_z0);
    cudaGetSymbolAddress((void**)&WTb,  g_WTd);

    const size_t enc_smem = 31072 * sizeof(float);   // 124288 B
    cudaFuncSetAttribute(enc_lstm_kernel, cudaFuncAttributeMaxDynamicSharedMemorySize, (int)enc_smem);
    const size_t soc_smem = 52816 * sizeof(float);   // 211264 B
    cudaFuncSetAttribute(social_kernel, cudaFuncAttributeMaxDynamicSharedMemorySize, (int)soc_smem);

    // ego encoder (192 rows) and neighbor encoder (36864 rows)
    enc_lstm_kernel<<<NNODES / 64, 512, enc_smem>>>(obs_traj, Wip, bip, Wih_e, Whh_e,
                                                    bih_e, bhh_e, He, NNODES);
    enc_lstm_kernel<<<PP / 64, 512, enc_smem>>>(obs_ngbrs, Wip, bip, Wih_e, Whh_e,
                                                bih_e, bhh_e, Hn, PP);
    dyn_kernel<<<(NNODES * DYN + 255) / 256, 256>>>(He, Wdyn, bdyn, dynb);
    social_kernel<<<NNODES, 384, soc_smem>>>(Hn, midx, Wc1, bc1, Wc2, bc2, socb);
    z0_kernel<<<(NNODES * 512 + 255) / 256, 256>>>(dynb, socb, Wih_d, bih_d, bhh_d, z0b);
    transpose_whhd<<<(512 * 128 + 255) / 256, 256>>>(Whh_d, WTb);
    dec_kernel<<<NNODES / 2, 512>>>(z0b, WTb, Wop, bop, out);
}

// round 3
// speedup vs baseline: 2.4272x; 2.4272x over previous
#include <cuda_runtime.h>
#include <cuda_bf16.h>
#include <cstdint>
#include <cstddef>

#define OBS_LEN 16
#define PRED_LEN 25
#define NNODES 192
#define PP (NNODES * NNODES)

// ---------------- device-global scratch ----------------
__device__ float g_Hngbr[PP * 64];          // 9.4 MB
__device__ float g_Hego[NNODES * 64];
__device__ float g_dyn[NNODES * 32];
__device__ float g_soc[NNODES * 144];
__device__ float g_z0[NNODES * 512];
__device__ float g_WTd[128 * 512];          // Whh_d transposed [k][j]
__device__ float g_w1t[576 * 64];           // Wc1 transposed [c*9+u*3+v][o]
__device__ float g_w2t[576 * 16];

__device__ __forceinline__ float sigf(float x) { return __fdividef(1.f, 1.f + __expf(-x)); }
__device__ __forceinline__ float tanhx(float x) {
    float e = __expf(2.f * x);
    return 1.f - __fdividef(2.f, e + 1.f);
}
__device__ __forceinline__ float lrelu(float x) { return x >= 0.f ? x : 0.1f * x; }

__device__ __forceinline__ uint32_t tf32u(float x) {
    uint32_t u;
    asm("cvt.rna.tf32.f32 %0, %1;" : "=r"(u) : "f"(x));
    return u;
}

// mma.sync m16n8k8 tf32 (sm_80 base feature -> compiles at .target sm_103)
__device__ __forceinline__ void mma8(float* d, const uint32_t* a, const uint32_t* b) {
    asm volatile(
        "mma.sync.aligned.m16n8k8.row.col.f32.tf32.tf32.f32 "
        "{%0,%1,%2,%3}, {%4,%5,%6,%7}, {%8,%9}, {%0,%1,%2,%3};"
        : "+f"(d[0]), "+f"(d[1]), "+f"(d[2]), "+f"(d[3])
        : "r"(a[0]), "r"(a[1]), "r"(a[2]), "r"(a[3]), "r"(b[0]), "r"(b[1]));
}

// ================= encoder LSTM via mma.sync tf32 =================
// 579 blocks x 256 thr (8 warps). Blocks [0,576): neighbor rows (64/block);
// [576,579): ego rows. M=64 rows, N=256 gate-cols, K=96=[emb32|h64].
// Column permutation: col = 32*warp + 8*j + cc ; unit = 8*warp+2*j+(cc>>2),
// gate = cc&3 (i,f,g,o). Weights held in registers across the whole time loop.
#define A_STRIDE 100
__global__ void __launch_bounds__(256) enc_mma_kernel(
    const float* __restrict__ xng, const float* __restrict__ xego,
    const float* __restrict__ Wip, const float* __restrict__ bip,
    const float* __restrict__ Wih, const float* __restrict__ Whh,
    const float* __restrict__ bih, const float* __restrict__ bhh,
    float* __restrict__ Hng, float* __restrict__ Hego)
{
    __shared__ float As[64 * A_STRIDE];     // [row][k], k=0..31 emb, 32..95 h
    __shared__ float bsum[256];
    __shared__ float sWip[64], sbip[32];

    const float* x; float* Hout; int tot, r0;
    if (blockIdx.x < 576) { x = xng;  Hout = Hng;  tot = PP;     r0 = blockIdx.x * 64; }
    else                  { x = xego; Hout = Hego; tot = NNODES; r0 = (blockIdx.x - 576) * 64; }

    const int tid = threadIdx.x, warp = tid >> 5, lane = tid & 31;
    const int gid = lane >> 2, tig = lane & 3;
    const int oddl = lane & 1;

    // --- stage small params ---
    if (tid < 256) bsum[tid] = bih[tid] + bhh[tid];
    if (tid < 64) sWip[tid] = Wip[tid];
    if (tid < 32) sbip[tid] = bip[tid];
    // zero h region (k = 32..96) : 64 rows x 64 cols
    for (int i = tid; i < 64 * 64; i += 256)
        As[(i >> 6) * A_STRIDE + 32 + (i & 63)] = 0.f;

    // --- persistent B fragments (weights, tf32) ---
    uint32_t breg[4][12][2];
#pragma unroll
    for (int j = 0; j < 4; ++j) {
        const int unit = 8 * warp + 2 * j + (gid >> 2);
        const int gate = gid & 3;
        const int z = gate * 64 + unit;
        const float* wih = Wih + z * 32;
        const float* whh = Whh + z * 64;
#pragma unroll
        for (int t = 0; t < 12; ++t) {
            const int k0 = 8 * t + tig, k1 = k0 + 4;
            float v0 = (k0 < 32) ? wih[k0] : whh[k0 - 32];
            float v1 = (k1 < 32) ? wih[k1] : whh[k1 - 32];
            breg[j][t][0] = tf32u(v0);
            breg[j][t][1] = tf32u(v1);
        }
    }

    float cst[4][4], hfin[4][4];
#pragma unroll
    for (int i = 0; i < 4; ++i)
#pragma unroll
        for (int j = 0; j < 4; ++j) { cst[i][j] = 0.f; hfin[i][j] = 0.f; }

    // per-thread epilogue ownership
    const int urow_off = gid + (oddl ? 8 : 0);          // row within m-tile
    const int uoff = (lane >> 1) & 1;                   // unit offset within j-pair

    const int erow = tid >> 2;                          // emb: row handled
    const int ecb = (tid & 3) * 8;                      // emb: first col

    for (int ts = 0; ts < OBS_LEN; ++ts) {
        // ---- input embedding -> As[:,0:32] (tf32-rounded) ----
        {
            const float* xt = x + ((size_t)ts * tot + r0 + erow) * 2;
            float x0 = xt[0], x1 = xt[1];
#pragma unroll
            for (int e = 0; e < 8; ++e) {
                int k = ecb + e;
                float v = fmaf(sWip[k * 2], x0, fmaf(sWip[k * 2 + 1], x1, sbip[k]));
                ((uint32_t*)As)[erow * A_STRIDE + k] = tf32u(lrelu(v));
            }
        }
        __syncthreads();   // A (emb + prev h) ready

        // ---- GEMM: acc = bias + A @ W ----
        float acc[4][4][4];
#pragma unroll
        for (int j = 0; j < 4; ++j) {
            const int cc0 = 2 * tig;
            const int unit_b = 8 * warp + 2 * j + (cc0 >> 2);
            const float b0v = bsum[(cc0 & 3) * 64 + unit_b];
            const float b1v = bsum[((cc0 + 1) & 3) * 64 + unit_b];
#pragma unroll
            for (int i = 0; i < 4; ++i) {
                acc[i][j][0] = b0v; acc[i][j][1] = b1v;
                acc[i][j][2] = b0v; acc[i][j][3] = b1v;
            }
        }
        const uint32_t* Au = (const uint32_t*)As;
#pragma unroll
        for (int t = 0; t < 12; ++t) {
            uint32_t a[4][4];
#pragma unroll
            for (int i = 0; i < 4; ++i) {
                const int r = 16 * i + gid;
                a[i][0] = Au[r * A_STRIDE + 8 * t + tig];
                a[i][1] = Au[(r + 8) * A_STRIDE + 8 * t + tig];
                a[i][2] = Au[r * A_STRIDE + 8 * t + 4 + tig];
                a[i][3] = Au[(r + 8) * A_STRIDE + 8 * t + 4 + tig];
            }
#pragma unroll
            for (int i = 0; i < 4; ++i)
#pragma unroll
                for (int j = 0; j < 4; ++j)
                    mma8(acc[i][j], a[i], breg[j][t]);
        }
        __syncthreads();   // all warps done reading As

        // ---- epilogue: gate exchange + LSTM cell update + write h ----
#pragma unroll
        for (int i = 0; i < 4; ++i) {
#pragma unroll
            for (int j = 0; j < 4; ++j) {
                float e0 = __shfl_xor_sync(0xffffffffu, acc[i][j][0], 1);
                float e1 = __shfl_xor_sync(0xffffffffu, acc[i][j][1], 1);
                float e2 = __shfl_xor_sync(0xffffffffu, acc[i][j][2], 1);
                float e3 = __shfl_xor_sync(0xffffffffu, acc[i][j][3], 1);
                float zi = oddl ? e2 : acc[i][j][0];
                float zf = oddl ? e3 : acc[i][j][1];
                float zg = oddl ? acc[i][j][2] : e0;
                float zo = oddl ? acc[i][j][3] : e1;
                float cs = sigf(zf) * cst[i][j] + sigf(zi) * tanhx(zg);
                cst[i][j] = cs;
                float h = sigf(zo) * tanhx(cs);
                hfin[i][j] = h;
                const int rowl = 16 * i + urow_off;
                const int ug = 8 * warp + 2 * j + uoff;
                ((uint32_t*)As)[rowl * A_STRIDE + 32 + ug] = tf32u(h);
            }
        }
        // next iteration's emb-write + __syncthreads orders these h-writes
    }

    // ---- final hidden state (exact fp32) ----
#pragma unroll
    for (int i = 0; i < 4; ++i) {
#pragma unroll
        for (int j = 0; j < 4; ++j) {
            const int grow = r0 + 16 * i + urow_off;
            const int ug = 8 * warp + 2 * j + uoff;
            Hout[(size_t)grow * 64 + ug] = hfin[i][j];
        }
    }
}

// ================= weight prep (one-time transposes) =================
__global__ void prep_kernel(const float* __restrict__ Wc1, const float* __restrict__ Wc2,
                            const float* __restrict__ Whh_d)
{
    int i = blockIdx.x * blockDim.x + threadIdx.x;
    if (i < 36864) { int o = i / 576, r = i - o * 576; g_w1t[r * 64 + o] = Wc1[i]; }
    if (i < 9216)  { int o = i / 576, r = i - o * 576; g_w2t[r * 16 + o] = Wc2[i]; }
    if (i < 512 * 128) { int j = i >> 7, k = i & 127; g_WTd[k * 512 + j] = Whh_d[i]; }
}

// ================= traj_enc = lrelu(H_ego @ Wdyn^T + b) =================
__global__ void dyn_kernel(const float* __restrict__ H, const float* __restrict__ Wdyn,
                           const float* __restrict__ bdyn, float* __restrict__ out)
{
    int i = blockIdx.x * blockDim.x + threadIdx.x;
    if (i >= NNODES * 32) return;
    int n = i >> 5, j = i & 31;
    float a = bdyn[j];
    const float* h = H + n * 64;
    const float* w = Wdyn + j * 64;
#pragma unroll 8
    for (int k = 0; k < 64; ++k) a = fmaf(w[k], h[k], a);
    out[i] = lrelu(a);
}

// ================= social: gather + conv1 + conv2 + maxpool =================
__global__ void __launch_bounds__(384) social_kernel(
    const float* __restrict__ Hn, const int* __restrict__ midx,
    const float* __restrict__ bc1, const float* __restrict__ bc2,
    float* __restrict__ socout)
{
    __shared__ float in_s[4096];      // [c][gw*8+gh]
    __shared__ float mid[64 * 36];    // [o][g*6+q]
    __shared__ float c2s[256];
    __shared__ float bc1s[64], bc2s[16];

    int tid = threadIdx.x, b = blockIdx.x;
    for (int i = tid; i < 4096; i += 384) {
        int e = i & 63; int cell = i >> 6;
        int gh = cell >> 3, gw = cell & 7;
        int p = midx[b * 64 + cell];
        in_s[e * 64 + gw * 8 + gh] = Hn[p * 64 + e];
    }
    if (tid < 64) bc1s[tid] = bc1[tid];
    if (tid < 16) bc2s[tid] = bc2[tid];
    __syncthreads();

    { // conv1: [64,8,8]->[64,6,6]; thread = (out row g, out channel o)
        int g = tid >> 6, o = tid & 63;
        float acc[6];
#pragma unroll
        for (int q = 0; q < 6; ++q) acc[q] = bc1s[o];
        for (int c = 0; c < 64; ++c) {
#pragma unroll
            for (int u = 0; u < 3; ++u) {
                float iv[8];
#pragma unroll
                for (int j = 0; j < 8; ++j) iv[j] = in_s[c * 64 + (g + u) * 8 + j];
#pragma unroll
                for (int v = 0; v < 3; ++v) {
                    float w = __ldg(&g_w1t[(c * 9 + u * 3 + v) * 64 + o]);
#pragma unroll
                    for (int q = 0; q < 6; ++q) acc[q] = fmaf(w, iv[q + v], acc[q]);
                }
            }
        }
#pragma unroll
        for (int q = 0; q < 6; ++q) mid[o * 36 + g * 6 + q] = lrelu(acc[q]);
    }
    __syncthreads();

    if (tid < 256) { // conv2: [64,6,6]->[16,4,4]
        int o = tid >> 4, pos = tid & 15; int p = pos >> 2, q = pos & 3;
        float acc = bc2s[o];
        for (int c = 0; c < 64; ++c) {
#pragma unroll
            for (int u = 0; u < 3; ++u)
#pragma unroll
                for (int v = 0; v < 3; ++v)
                    acc = fmaf(mid[c * 36 + (p + u) * 6 + (q + v)],
                               __ldg(&g_w2t[(c * 9 + u * 3 + v) * 16 + o]), acc);
        }
        c2s[tid] = lrelu(acc);
    }
    __syncthreads();

    if (tid < 144) { // maxpool 2x2 s1 -> [16,3,3]
        int o = tid / 9, pq = tid - o * 9; int p = pq / 3, q = pq - p * 3;
        const float* base = c2s + o * 16;
        float m = fmaxf(fmaxf(base[p * 4 + q], base[p * 4 + q + 1]),
                        fmaxf(base[(p + 1) * 4 + q], base[(p + 1) * 4 + q + 1]));
        socout[b * 144 + tid] = m;
    }
}

// ================= z0 = Wih_d @ [traj_enc|soc] + bih + bhh =================
__global__ void z0_kernel(const float* __restrict__ dyn, const float* __restrict__ soc,
                          const float* __restrict__ Wih_d, const float* __restrict__ bih_d,
                          const float* __restrict__ bhh_d, float* __restrict__ z0)
{
    int i = blockIdx.x * blockDim.x + threadIdx.x;
    if (i >= NNODES * 512) return;
    int n = i >> 9, j = i & 511;
    float a = bih_d[j] + bhh_d[j];
    const float* w = Wih_d + j * 176;
    const float* d = dyn + n * 32;
    const float* s = soc + n * 144;
#pragma unroll 4
    for (int k = 0; k < 32; ++k) a = fmaf(w[k], d[k], a);
#pragma unroll 4
    for (int k = 0; k < 144; ++k) a = fmaf(w[32 + k], s[k], a);
    z0[i] = a;
}

// ================= decoder: 3 rows/block, 64 blocks =================
__global__ void __launch_bounds__(512) dec_kernel(
    const float* __restrict__ z0, const float* __restrict__ Wop,
    const float* __restrict__ bop, float* __restrict__ out)
{
    __shared__ float h_s[3][128];
    __shared__ float z_s[3][512];
    int tid = threadIdx.x;
    int b0 = blockIdx.x * 3;
    float zin0 = z0[(b0 + 0) * 512 + tid];
    float zin1 = z0[(b0 + 1) * 512 + tid];
    float zin2 = z0[(b0 + 2) * 512 + tid];
    float c = 0.f;
    if (tid < 384) h_s[tid >> 7][tid & 127] = 0.f;
    __syncthreads();

    for (int t = 0; t < PRED_LEN; ++t) {
        float a0 = zin0, a1 = zin1, a2 = zin2;
#pragma unroll 8
        for (int k = 0; k < 128; ++k) {
            float w = g_WTd[k * 512 + tid];
            a0 = fmaf(w, h_s[0][k], a0);
            a1 = fmaf(w, h_s[1][k], a1);
            a2 = fmaf(w, h_s[2][k], a2);
        }
        z_s[0][tid] = a0; z_s[1][tid] = a1; z_s[2][tid] = a2;
        __syncthreads();
        if (tid < 384) {
            int r = tid >> 7, m = tid & 127;
            float zi = z_s[r][m], zf = z_s[r][128 + m];
            float zg = z_s[r][256 + m], zo = z_s[r][384 + m];
            c = sigf(zf) * c + sigf(zi) * tanhx(zg);
            h_s[r][m] = sigf(zo) * tanhx(c);
        }
        __syncthreads();
        int wp = tid >> 5, ln = tid & 31;
        if (wp < 15) {  // 3 rows x 5 outputs
            int r = wp / 5, oi = wp - r * 5;
            float a = 0.f;
#pragma unroll
            for (int k = ln; k < 128; k += 32) a = fmaf(Wop[oi * 128 + k], h_s[r][k], a);
#pragma unroll
            for (int s = 16; s; s >>= 1) a += __shfl_down_sync(0xffffffffu, a, s);
            if (ln == 0) {
                a += bop[oi];
                float v = (oi == 2 || oi == 3) ? __expf(a) : (oi == 4 ? tanhx(a) : a);
                out[((size_t)t * NNODES + b0 + r) * 5 + oi] = v;
            }
        }
    }
}

// ================= launcher =================
extern "C" void kernel_launch(void* const* d_in, const int* in_sizes, int n_in,
                              void* d_out, int out_size)
{
    int wi = (n_in > 6 && in_sizes[6] == 1) ? 7 : 6;

    const float* obs_traj  = (const float*)d_in[0];
    const float* obs_ngbrs = (const float*)d_in[1];
    const int*   midx      = (const int*)d_in[3];
    const float* Wip   = (const float*)d_in[wi + 0];
    const float* bip   = (const float*)d_in[wi + 1];
    const float* Wih_e = (const float*)d_in[wi + 2];
    const float* Whh_e = (const float*)d_in[wi + 3];
    const float* bih_e = (const float*)d_in[wi + 4];
    const float* bhh_e = (const float*)d_in[wi + 5];
    const float* Wdyn  = (const float*)d_in[wi + 6];
    const float* bdyn  = (const float*)d_in[wi + 7];
    const float* Wc1   = (const float*)d_in[wi + 8];
    const float* bc1   = (const float*)d_in[wi + 9];
    const float* Wc2   = (const float*)d_in[wi + 10];
    const float* bc2   = (const float*)d_in[wi + 11];
    const float* Wih_d = (const float*)d_in[wi + 12];
    const float* Whh_d = (const float*)d_in[wi + 13];
    const float* bih_d = (const float*)d_in[wi + 14];
    const float* bhh_d = (const float*)d_in[wi + 15];
    const float* Wop   = (const float*)d_in[wi + 16];
    const float* bop   = (const float*)d_in[wi + 17];
    float* out = (float*)d_out;

    float *Hn, *He, *dynb, *socb, *z0b;
    cudaGetSymbolAddress((void**)&Hn,   g_Hngbr);
    cudaGetSymbolAddress((void**)&He,   g_Hego);
    cudaGetSymbolAddress((void**)&dynb, g_dyn);
    cudaGetSymbolAddress((void**)&socb, g_soc);
    cudaGetSymbolAddress((void**)&z0b,  g_z0);

    prep_kernel<<<256, 256>>>(Wc1, Wc2, Whh_d);
    enc_mma_kernel<<<579, 256>>>(obs_ngbrs, obs_traj, Wip, bip,
                                 Wih_e, Whh_e, bih_e, bhh_e, Hn, He);
    dyn_kernel<<<(NNODES * 32 + 255) / 256, 256>>>(He, Wdyn, bdyn, dynb);
    social_kernel<<<NNODES, 384>>>(Hn, midx, bc1, bc2, socb);
    z0_kernel<<<(NNODES * 512 + 255) / 256, 256>>>(dynb, socb, Wih_d, bih_d, bhh_d, z0b);
    dec_kernel<<<NNODES / 3, 512>>>(z0b, Wop, bop, out);
}

// round 6
// speedup vs baseline: 3.0822x; 1.2699x over previous
#include <cuda_runtime.h>
#include <cuda_bf16.h>
#include <cstdint>
#include <cstddef>

#define OBS_LEN 16
#define PRED_LEN 25
#define NNODES 192
#define PP (NNODES * NNODES)

// ---------------- device-global scratch ----------------
__device__ float g_Hngbr[PP * 64];          // 9.4 MB
__device__ float g_Hego[NNODES * 64];
__device__ float g_dyn[NNODES * 32];
__device__ float g_soc[NNODES * 144];
__device__ float g_z0[NNODES * 512];
__device__ float g_WTd[128 * 512];          // Whh_d transposed [k][j]
__device__ float g_w1t[576 * 64];           // Wc1 transposed [c*9+u*3+v][o]
__device__ float g_w2t[576 * 16];

__device__ __forceinline__ float sigf(float x) { return __fdividef(1.f, 1.f + __expf(-x)); }
__device__ __forceinline__ float tanhx(float x) {
    float e = __expf(2.f * x);
    return 1.f - __fdividef(2.f, e + 1.f);
}
__device__ __forceinline__ float tanha(float x) {
    float y;
    asm("tanh.approx.f32 %0, %1;" : "=f"(y) : "f"(x));
    return y;
}
__device__ __forceinline__ float siga(float x) {   // sigmoid via tanh.approx
    return fmaf(tanha(0.5f * x), 0.5f, 0.5f);
}
__device__ __forceinline__ float lrelu(float x) { return x >= 0.f ? x : 0.1f * x; }

__device__ __forceinline__ uint32_t tf32u(float x) {
    uint32_t u;
    asm("cvt.rna.tf32.f32 %0, %1;" : "=r"(u) : "f"(x));
    return u;
}

// mma.sync m16n8k8 tf32 (sm_80 base feature)
__device__ __forceinline__ void mma8(float* d, const uint32_t* a, const uint32_t* b) {
    asm volatile(
        "mma.sync.aligned.m16n8k8.row.col.f32.tf32.tf32.f32 "
        "{%0,%1,%2,%3}, {%4,%5,%6,%7}, {%8,%9}, {%0,%1,%2,%3};"
        : "+f"(d[0]), "+f"(d[1]), "+f"(d[2]), "+f"(d[3])
        : "r"(a[0]), "r"(a[1]), "r"(a[2]), "r"(a[3]), "r"(b[0]), "r"(b[1]));
}

// ================= encoder LSTM via mma.sync tf32 =================
// 579 blocks x 512 thr (16 warps, 4/SMSP). Blocks [0,576): neighbor rows
// (64/block); [576,579): ego. M=64 rows, N=256 gate-cols, K=96=[emb32|h64].
// Warp w owns cols 16w..16w+15 (j=0,1 tiles of n8).
// col = 16*warp + 8*j + cc ; unit = 4*warp + 2*j + (cc>>2), gate = cc&3.
#define A_STRIDE 100
__global__ void __launch_bounds__(512, 1) enc_mma_kernel(
    const float* __restrict__ xng, const float* __restrict__ xego,
    const float* __restrict__ Wip, const float* __restrict__ bip,
    const float* __restrict__ Wih, const float* __restrict__ Whh,
    const float* __restrict__ bih, const float* __restrict__ bhh,
    float* __restrict__ Hng, float* __restrict__ Hego)
{
    __shared__ float As[64 * A_STRIDE];     // [row][k], k=0..31 emb, 32..95 h
    __shared__ float bsum[256];
    __shared__ float sWip[64], sbip[32];

    const float* x; float* Hout; int tot, r0;
    if (blockIdx.x < 576) { x = xng;  Hout = Hng;  tot = PP;     r0 = blockIdx.x * 64; }
    else                  { x = xego; Hout = Hego; tot = NNODES; r0 = (blockIdx.x - 576) * 64; }

    const int tid = threadIdx.x, warp = tid >> 5, lane = tid & 31;
    const int gid = lane >> 2, tig = lane & 3;
    const int oddl = tig & 1;

    if (tid < 256) bsum[tid] = bih[tid] + bhh[tid];
    if (tid < 64) sWip[tid] = Wip[tid];
    if (tid < 32) sbip[tid] = bip[tid];
    for (int i = tid; i < 64 * 64; i += 512)
        As[(i >> 6) * A_STRIDE + 32 + (i & 63)] = 0.f;

    // persistent B fragments (weights, tf32): 48 regs
    uint32_t breg[2][12][2];
#pragma unroll
    for (int j = 0; j < 2; ++j) {
        const int unit = 4 * warp + 2 * j + (gid >> 2);
        const int gate = gid & 3;
        const int z = gate * 64 + unit;
        const float* wih = Wih + z * 32;
        const float* whh = Whh + z * 64;
#pragma unroll
        for (int t = 0; t < 12; ++t) {
            const int k0 = 8 * t + tig, k1 = k0 + 4;
            float v0 = (k0 < 32) ? wih[k0] : whh[k0 - 32];
            float v1 = (k1 < 32) ? wih[k1] : whh[k1 - 32];
            breg[j][t][0] = tf32u(v0);
            breg[j][t][1] = tf32u(v1);
        }
    }

    float cst[4][2];
#pragma unroll
    for (int i = 0; i < 4; ++i) { cst[i][0] = 0.f; cst[i][1] = 0.f; }

    const int urow_off = gid + (oddl ? 8 : 0);   // epilogue row within m16 tile
    const int uoff = tig >> 1;                   // epilogue unit offset

    const int erow = tid >> 3;                   // emb: row handled
    const int ecb = (tid & 7) * 4;               // emb: first col (4 cols)

    __syncthreads();                             // bsum ready
    // hoist loop-invariant bias loads out of the time loop
    float bload[2][2];
#pragma unroll
    for (int j = 0; j < 2; ++j) {
        const int cc0 = 2 * tig;
        const int unit_b = 4 * warp + 2 * j + (cc0 >> 2);
        bload[j][0] = bsum[(cc0 & 3) * 64 + unit_b];
        bload[j][1] = bsum[((cc0 + 1) & 3) * 64 + unit_b];
    }

    for (int ts = 0; ts < OBS_LEN; ++ts) {
        { // input embedding -> As[:,0:32] (tf32-rounded)
            const float* xt = x + ((size_t)ts * tot + r0 + erow) * 2;
            float x0 = xt[0], x1 = xt[1];
#pragma unroll
            for (int e = 0; e < 4; ++e) {
                int k = ecb + e;
                float v = fmaf(sWip[k * 2], x0, fmaf(sWip[k * 2 + 1], x1, sbip[k]));
                ((uint32_t*)As)[erow * A_STRIDE + k] = tf32u(lrelu(v));
            }
        }
        __syncthreads();   // A (emb + prev h) ready

        // GEMM: acc = bias + A @ W
        float acc[4][2][4];
#pragma unroll
        for (int j = 0; j < 2; ++j)
#pragma unroll
            for (int i = 0; i < 4; ++i) {
                acc[i][j][0] = bload[j][0]; acc[i][j][1] = bload[j][1];
                acc[i][j][2] = bload[j][0]; acc[i][j][3] = bload[j][1];
            }
        const uint32_t* Au = (const uint32_t*)As;
#pragma unroll
        for (int t = 0; t < 12; ++t) {
            uint32_t a[4][4];
#pragma unroll
            for (int i = 0; i < 4; ++i) {
                const int r = 16 * i + gid;
                a[i][0] = Au[r * A_STRIDE + 8 * t + tig];
                a[i][1] = Au[(r + 8) * A_STRIDE + 8 * t + tig];
                a[i][2] = Au[r * A_STRIDE + 8 * t + 4 + tig];
                a[i][3] = Au[(r + 8) * A_STRIDE + 8 * t + 4 + tig];
            }
#pragma unroll
            for (int i = 0; i < 4; ++i)
#pragma unroll
                for (int j = 0; j < 2; ++j)
                    mma8(acc[i][j], a[i], breg[j][t]);
        }
        __syncthreads();   // all warps done reading As

        // epilogue: gate exchange + LSTM cell + write h (tf32) back to A
#pragma unroll
        for (int i = 0; i < 4; ++i) {
#pragma unroll
            for (int j = 0; j < 2; ++j) {
                float e0 = __shfl_xor_sync(0xffffffffu, acc[i][j][0], 1);
                float e1 = __shfl_xor_sync(0xffffffffu, acc[i][j][1], 1);
                float e2 = __shfl_xor_sync(0xffffffffu, acc[i][j][2], 1);
                float e3 = __shfl_xor_sync(0xffffffffu, acc[i][j][3], 1);
                float zi = oddl ? e2 : acc[i][j][0];
                float zf = oddl ? e3 : acc[i][j][1];
                float zg = oddl ? acc[i][j][2] : e0;
                float zo = oddl ? acc[i][j][3] : e1;
                float cs = siga(zf) * cst[i][j] + siga(zi) * tanha(zg);
                cst[i][j] = cs;
                float h = siga(zo) * tanha(cs);
                const int rowl = 16 * i + urow_off;
                const int ug = 4 * warp + 2 * j + uoff;
                ((uint32_t*)As)[rowl * A_STRIDE + 32 + ug] = tf32u(h);
                if (ts == OBS_LEN - 1)
                    Hout[(size_t)(r0 + rowl) * 64 + ug] = h;
            }
        }
    }
}

// ================= weight prep (one-time transposes) =================
__global__ void prep_kernel(const float* __restrict__ Wc1, const float* __restrict__ Wc2,
                            const float* __restrict__ Whh_d)
{
    int i = blockIdx.x * blockDim.x + threadIdx.x;
    if (i < 36864) { int o = i / 576, r = i - o * 576; g_w1t[r * 64 + o] = Wc1[i]; }
    if (i < 9216)  { int o = i / 576, r = i - o * 576; g_w2t[r * 16 + o] = Wc2[i]; }
    if (i < 512 * 128) { int j = i >> 7, k = i & 127; g_WTd[k * 512 + j] = Whh_d[i]; }
}

// ================= traj_enc = lrelu(H_ego @ Wdyn^T + b) =================
__global__ void dyn_kernel(const float* __restrict__ H, const float* __restrict__ Wdyn,
                           const float* __restrict__ bdyn, float* __restrict__ out)
{
    int i = blockIdx.x * blockDim.x + threadIdx.x;
    if (i >= NNODES * 32) return;
    int n = i >> 5, j = i & 31;
    float a = bdyn[j];
    const float* h = H + n * 64;
    const float* w = Wdyn + j * 64;
#pragma unroll 8
    for (int k = 0; k < 64; ++k) a = fmaf(w[k], h[k], a);
    out[i] = lrelu(a);
}

// ================= social: gather + conv1 + conv2 + maxpool =================
// 192 blocks x 384 thr. Weights LDS-staged in 8-channel chunks (kills the
// LDG-issue floor); padded smem strides kill bank conflicts.
__global__ void __launch_bounds__(384) social_kernel(
    const float* __restrict__ Hn, const int* __restrict__ midx,
    const float* __restrict__ bc1, const float* __restrict__ bc2,
    float* __restrict__ socout)
{
    __shared__ float in_s[64 * 65];    // [c][gw*8+gh], stride 65
    __shared__ float wbuf[4608];       // weight staging chunk
    __shared__ float mid[64 * 37];     // [o][g*6+q], stride 37
    __shared__ float c2s[256];

    int tid = threadIdx.x, b = blockIdx.x;
    for (int i = tid; i < 4096; i += 384) {
        int e = i & 63; int cell = i >> 6;
        int gh = cell >> 3, gw = cell & 7;
        int p = midx[b * 64 + cell];
        in_s[e * 65 + gw * 8 + gh] = Hn[p * 64 + e];
    }
    __syncthreads();

    // conv1: thread = (g, o); acc over q; Wc1 chunk-staged in smem
    int g = tid >> 6, o = tid & 63;
    float acc[6];
    float b1 = bc1[o];
#pragma unroll
    for (int q = 0; q < 6; ++q) acc[q] = b1;
    for (int c0 = 0; c0 < 64; c0 += 8) {
        __syncthreads();
        for (int i = tid; i < 4608; i += 384) wbuf[i] = g_w1t[c0 * 576 + i];
        __syncthreads();
#pragma unroll
        for (int cl = 0; cl < 8; ++cl) {
            int c = c0 + cl;
#pragma unroll
            for (int u = 0; u < 3; ++u) {
                float iv[8];
#pragma unroll
                for (int jj = 0; jj < 8; ++jj) iv[jj] = in_s[c * 65 + (g + u) * 8 + jj];
#pragma unroll
                for (int v = 0; v < 3; ++v) {
                    float w = wbuf[cl * 576 + (u * 3 + v) * 64 + o];
#pragma unroll
                    for (int q = 0; q < 6; ++q) acc[q] = fmaf(w, iv[q + v], acc[q]);
                }
            }
        }
    }
#pragma unroll
    for (int q = 0; q < 6; ++q) mid[o * 37 + g * 6 + q] = lrelu(acc[q]);
    __syncthreads();

    // conv2: thread = (o2, pos) for tid<256; w2 chunk-staged
    float acc2 = 0.f;
    int o2 = tid >> 4, pos = tid & 15, p2 = pos >> 2, q2 = pos & 3;
    if (tid < 256) acc2 = bc2[o2];
    for (int c0 = 0; c0 < 64; c0 += 8) {
        __syncthreads();
        for (int i = tid; i < 1152; i += 384) wbuf[i] = g_w2t[c0 * 144 + i];
        __syncthreads();
        if (tid < 256) {
#pragma unroll
            for (int cl = 0; cl < 8; ++cl) {
                int c = c0 + cl;
#pragma unroll
                for (int u = 0; u < 3; ++u)
#pragma unroll
                    for (int v = 0; v < 3; ++v)
                        acc2 = fmaf(mid[c * 37 + (p2 + u) * 6 + (q2 + v)],
                                    wbuf[cl * 144 + (u * 3 + v) * 16 + o2], acc2);
            }
        }
    }
    if (tid < 256) c2s[tid] = lrelu(acc2);
    __syncthreads();

    if (tid < 144) {  // maxpool 2x2 s1 -> [16,3,3]
        int oo = tid / 9, pq = tid - oo * 9; int p = pq / 3, q = pq - p * 3;
        const float* base = c2s + oo * 16;
        float m = fmaxf(fmaxf(base[p * 4 + q], base[p * 4 + q + 1]),
                        fmaxf(base[(p + 1) * 4 + q], base[(p + 1) * 4 + q + 1]));
        socout[b * 144 + tid] = m;
    }
}

// ================= z0 = Wih_d @ [traj_enc|soc] + bih + bhh =================
__global__ void z0_kernel(const float* __restrict__ dyn, const float* __restrict__ soc,
                          const float* __restrict__ Wih_d, const float* __restrict__ bih_d,
                          const float* __restrict__ bhh_d, float* __restrict__ z0)
{
    int i = blockIdx.x * blockDim.x + threadIdx.x;
    if (i >= NNODES * 512) return;
    int n = i >> 9, j = i & 511;
    float a = bih_d[j] + bhh_d[j];
    const float* w = Wih_d + j * 176;
    const float* d = dyn + n * 32;
    const float* s = soc + n * 144;
#pragma unroll 4
    for (int k = 0; k < 32; ++k) a = fmaf(w[k], d[k], a);
#pragma unroll 4
    for (int k = 0; k < 144; ++k) a = fmaf(w[32 + k], s[k], a);
    z0[i] = a;
}

// ================= decoder: 192 blocks x 1 row (all SMs busy) =================
__global__ void __launch_bounds__(512) dec_kernel(
    const float* __restrict__ z0, const float* __restrict__ Wop,
    const float* __restrict__ bop, float* __restrict__ out)
{
    __shared__ float h_s[128];
    __shared__ float z_s[512];
    int tid = threadIdx.x, b = blockIdx.x;
    float zin = z0[b * 512 + tid];
    float c = 0.f;
    if (tid < 128) h_s[tid] = 0.f;
    __syncthreads();

    for (int t = 0; t < PRED_LEN; ++t) {
        float a = zin;
#pragma unroll
        for (int k = 0; k < 128; ++k)
            a = fmaf(g_WTd[k * 512 + tid], h_s[k], a);
        z_s[tid] = a;
        __syncthreads();
        if (tid < 128) {
            float zi = z_s[tid], zf = z_s[128 + tid];
            float zg = z_s[256 + tid], zo = z_s[384 + tid];
            c = sigf(zf) * c + sigf(zi) * tanhx(zg);
            h_s[tid] = sigf(zo) * tanhx(c);
        }
        __syncthreads();
        if (tid < 160) {  // 5 warps: output projection
            int oi = tid >> 5, ln = tid & 31;
            float a2 = 0.f;
#pragma unroll
            for (int k = ln; k < 128; k += 32) a2 = fmaf(Wop[oi * 128 + k], h_s[k], a2);
#pragma unroll
            for (int s = 16; s; s >>= 1) a2 += __shfl_down_sync(0xffffffffu, a2, s);
            if (ln == 0) {
                a2 += bop[oi];
                float v = (oi == 2 || oi == 3) ? __expf(a2) : (oi == 4 ? tanhx(a2) : a2);
                out[((size_t)t * NNODES + b) * 5 + oi] = v;
            }
        }
    }
}

// ================= launcher =================
extern "C" void kernel_launch(void* const* d_in, const int* in_sizes, int n_in,
                              void* d_out, int out_size)
{
    int wi = (n_in > 6 && in_sizes[6] == 1) ? 7 : 6;

    const float* obs_traj  = (const float*)d_in[0];
    const float* obs_ngbrs = (const float*)d_in[1];
    const int*   midx      = (const int*)d_in[3];
    const float* Wip   = (const float*)d_in[wi + 0];
    const float* bip   = (const float*)d_in[wi + 1];
    const float* Wih_e = (const float*)d_in[wi + 2];
    const float* Whh_e = (const float*)d_in[wi + 3];
    const float* bih_e = (const float*)d_in[wi + 4];
    const float* bhh_e = (const float*)d_in[wi + 5];
    const float* Wdyn  = (const float*)d_in[wi + 6];
    const float* bdyn  = (const float*)d_in[wi + 7];
    const float* Wc1   = (const float*)d_in[wi + 8];
    const float* bc1   = (const float*)d_in[wi + 9];
    const float* Wc2   = (const float*)d_in[wi + 10];
    const float* bc2   = (const float*)d_in[wi + 11];
    const float* Wih_d = (const float*)d_in[wi + 12];
    const float* Whh_d = (const float*)d_in[wi + 13];
    const float* bih_d = (const float*)d_in[wi + 14];
    const float* bhh_d = (const float*)d_in[wi + 15];
    const float* Wop   = (const float*)d_in[wi + 16];
    const float* bop   = (const float*)d_in[wi + 17];
    float* out = (float*)d_out;

    float *Hn, *He, *dynb, *socb, *z0b;
    cudaGetSymbolAddress((void**)&Hn,   g_Hngbr);
    cudaGetSymbolAddress((void**)&He,   g_Hego);
    cudaGetSymbolAddress((void**)&dynb, g_dyn);
    cudaGetSymbolAddress((void**)&socb, g_soc);
    cudaGetSymbolAddress((void**)&z0b,  g_z0);

    prep_kernel<<<256, 256>>>(Wc1, Wc2, Whh_d);
    enc_mma_kernel<<<579, 512>>>(obs_ngbrs, obs_traj, Wip, bip,
                                 Wih_e, Whh_e, bih_e, bhh_e, Hn, He);
    dyn_kernel<<<(NNODES * 32 + 255) / 256, 256>>>(He, Wdyn, bdyn, dynb);
    social_kernel<<<NNODES, 384>>>(Hn, midx, bc1, bc2, socb);
    z0_kernel<<<(NNODES * 512 + 255) / 256, 256>>>(dynb, socb, Wih_d, bih_d, bhh_d, z0b);
    dec_kernel<<<NNODES, 512>>>(z0b, Wop, bop, out);
}